// round 9
// baseline (speedup 1.0000x reference)
#include <cuda_runtime.h>
#include <cuda_bf16.h>
#include <cstdint>

#define BATCH   2
#define SEQLEN  2048
#define DMODEL  1024
#define DSTATE  16
#define DTRANK  64
#define NROWS   (BATCH * SEQLEN)          // 4096
#define NCHUNK  64
#define CLEN    (SEQLEN / NCHUNK)         // 32
#define NCH     (BATCH * DMODEL)          // 2048
#define NGRP    (NCH * NCHUNK)            // 131072
#define KSPLIT  4

typedef unsigned long long ull;

// ---------------------------------------------------------------------------
// f32x2 packed-math helpers (bit-exact IEEE fp32 per lane)
// ---------------------------------------------------------------------------
__device__ __forceinline__ ull pack2(float lo, float hi) {
    ull r; asm("mov.b64 %0, {%1, %2};" : "=l"(r) : "f"(lo), "f"(hi)); return r;
}
__device__ __forceinline__ void unpack2(ull v, float& lo, float& hi) {
    asm("mov.b64 {%0, %1}, %2;" : "=f"(lo), "=f"(hi) : "l"(v));
}
__device__ __forceinline__ ull fma2(ull a, ull b, ull c) {
    ull d; asm("fma.rn.f32x2 %0, %1, %2, %3;" : "=l"(d) : "l"(a), "l"(b), "l"(c)); return d;
}
__device__ __forceinline__ ull mul2(ull a, ull b) {
    ull d; asm("mul.rn.f32x2 %0, %1, %2;" : "=l"(d) : "l"(a), "l"(b)); return d;
}

// ---------------------------------------------------------------------------
// Device scratch.  Boundary-state arrays are CHUNK-MAJOR: [chunk][ch][n]
// ---------------------------------------------------------------------------
__device__ float  g_wp [96 * DMODEL];
__device__ float  g_A  [DMODEL * DSTATE];
__device__ float  g_dpp[(size_t)KSPLIT * NROWS * DTRANK];
__device__ float  g_bcp[(size_t)KSPLIT * NROWS * 32];
__device__ float  g_bp [(size_t)NROWS * DSTATE];
__device__ float  g_cp [(size_t)NROWS * DSTATE];
__device__ float2 g_dd [(size_t)NROWS * DMODEL];
__device__ float  g_hl [(size_t)NGRP * DSTATE];
__device__ float  g_T  [(size_t)NGRP];
__device__ float  g_hin[(size_t)NGRP * DSTATE];

// ---------------------------------------------------------------------------
// K0: fold sigmoid(trend) into x_proj_w; precompute A = -exp(A_log)
// ---------------------------------------------------------------------------
__global__ __launch_bounds__(256)
void prep_kernel(const float* __restrict__ W, const float* __restrict__ te,
                 const float* __restrict__ A_log)
{
    int idx = blockIdx.x * 256 + threadIdx.x;
    if (idx < 96 * DMODEL) {
        int k = idx & (DMODEL - 1);
        float sg = 1.f / (1.f + __expf(-te[k]));
        g_wp[idx] = W[idx] * sg;
    }
    if (idx < DMODEL * DSTATE) {
        g_A[idx] = -__expf(A_log[idx]);
    }
}

// ---------------------------------------------------------------------------
// K1: split-K GEMM1 partials.  BM=64, BN=96, BK=64, 256 thr, tile 4x6 (f32x2)
// ---------------------------------------------------------------------------
__global__ __launch_bounds__(256)
void gemm1_kernel(const float* __restrict__ x)
{
    __shared__ float As[64][68];
    __shared__ float Ws[64][98];

    const int tid  = threadIdx.x;
    const int row0 = blockIdx.x * 64;
    const int ks   = blockIdx.y;
    const int ty   = tid >> 4;
    const int tx   = tid & 15;

    ull accp[4][3];
#pragma unroll
    for (int i = 0; i < 4; i++)
#pragma unroll
        for (int j = 0; j < 3; j++) accp[i][j] = 0ull;

    for (int kk = 0; kk < 256; kk += 64) {
        const int kt = ks * 256 + kk;
#pragma unroll
        for (int i = 0; i < 4; i++) {
            int e  = i * 256 + tid;
            int r  = e >> 4;
            int k4 = e & 15;
            float4 v = *(const float4*)&x[(size_t)(row0 + r) * DMODEL + kt + k4 * 4];
            As[k4 * 4 + 0][r] = v.x;
            As[k4 * 4 + 1][r] = v.y;
            As[k4 * 4 + 2][r] = v.z;
            As[k4 * 4 + 3][r] = v.w;
        }
#pragma unroll
        for (int i = 0; i < 6; i++) {
            int e  = i * 256 + tid;
            int c  = e >> 4;
            int k4 = e & 15;
            float4 v = *(const float4*)&g_wp[(size_t)c * DMODEL + kt + k4 * 4];
            Ws[k4 * 4 + 0][c] = v.x;
            Ws[k4 * 4 + 1][c] = v.y;
            Ws[k4 * 4 + 2][c] = v.z;
            Ws[k4 * 4 + 3][c] = v.w;
        }
        __syncthreads();

#pragma unroll 8
        for (int k = 0; k < 64; k++) {
            float4 a4 = *(const float4*)&As[k][ty * 4];
            ull ap[4];
            ap[0] = pack2(a4.x, a4.x);
            ap[1] = pack2(a4.y, a4.y);
            ap[2] = pack2(a4.z, a4.z);
            ap[3] = pack2(a4.w, a4.w);
            ull wp0 = *(const ull*)&Ws[k][tx * 6 + 0];
            ull wp1 = *(const ull*)&Ws[k][tx * 6 + 2];
            ull wp2 = *(const ull*)&Ws[k][tx * 6 + 4];
#pragma unroll
            for (int i = 0; i < 4; i++) {
                accp[i][0] = fma2(ap[i], wp0, accp[i][0]);
                accp[i][1] = fma2(ap[i], wp1, accp[i][1]);
                accp[i][2] = fma2(ap[i], wp2, accp[i][2]);
            }
        }
        __syncthreads();
    }

#pragma unroll
    for (int i = 0; i < 4; i++) {
        int r = row0 + ty * 4 + i;
#pragma unroll
        for (int jp = 0; jp < 3; jp++) {
            float v0, v1;
            unpack2(accp[i][jp], v0, v1);
            int c = tx * 6 + jp * 2;
#pragma unroll
            for (int h = 0; h < 2; h++) {
                float v = h ? v1 : v0;
                int cc = c + h;
                if (cc < DTRANK)
                    g_dpp[((size_t)ks * NROWS + r) * DTRANK + cc] = v;
                else
                    g_bcp[((size_t)ks * NROWS + r) * 32 + (cc - DTRANK)] = v;
            }
        }
    }
}

// ---------------------------------------------------------------------------
// K2 (fused GEMM2 + chunk-local scan), chunk-major state output.
// ---------------------------------------------------------------------------
__global__ __launch_bounds__(256)
void gemm2s_kernel(const float* __restrict__ x,
                   const float* __restrict__ dtw,
                   const float* __restrict__ dtb,
                   const float* __restrict__ te)
{
    __shared__ __align__(16) char smraw[45568];
    float  (*dps)[34]  = (float (*)[34]) (smraw);                // 8704 B
    float  (*ws)[132]  = (float (*)[132])(smraw + 8704);         // 33792 B
    float2 (*sdd)[132] = (float2(*)[132])(smraw + 8704);         // union w/ ws
    float  (*Bs)[16]   = (float (*)[16]) (smraw + 42496);        // 2048 B
    float*  ssg        = (float*)(smraw + 44544);                // 512 B
    float*  sdtb       = (float*)(smraw + 45056);                // 512 B

    const int tid  = threadIdx.x;
    const int row0 = blockIdx.x * 32;
    const int by   = blockIdx.y;
    const int ty   = tid >> 4;
    const int tx   = tid & 15;

    // ---- precompute per-column sigmoid(te) and dtb ----
    if (tid < 128) {
        float tev = te[by * 128 + tid];
        ssg[tid]  = 1.f / (1.f + __expf(-tev));
        sdtb[tid] = dtb[by * 128 + tid];
    }

    // ---- Phase A: sum partials ----
#pragma unroll
    for (int i = 0; i < 2; i++) {
        int e  = i * 256 + tid;
        int r  = e >> 4;
        int k4 = e & 15;
        float4 s = make_float4(0.f, 0.f, 0.f, 0.f);
#pragma unroll
        for (int ks = 0; ks < KSPLIT; ks++) {
            float4 v = *(const float4*)&g_dpp[((size_t)ks * NROWS + row0 + r) * DTRANK + k4 * 4];
            s.x += v.x; s.y += v.y; s.z += v.z; s.w += v.w;
        }
        dps[k4 * 4 + 0][r] = s.x;
        dps[k4 * 4 + 1][r] = s.y;
        dps[k4 * 4 + 2][r] = s.z;
        dps[k4 * 4 + 3][r] = s.w;
    }
    {
        int r  = tid >> 3;
        int c4 = tid & 7;
        float4 s = make_float4(0.f, 0.f, 0.f, 0.f);
#pragma unroll
        for (int ks = 0; ks < KSPLIT; ks++) {
            float4 v = *(const float4*)&g_bcp[((size_t)ks * NROWS + row0 + r) * 32 + c4 * 4];
            s.x += v.x; s.y += v.y; s.z += v.z; s.w += v.w;
        }
        if (c4 < 4) {
            *(float4*)&Bs[r][c4 * 4] = s;
            if (by == 0) *(float4*)&g_bp[(size_t)(row0 + r) * DSTATE + c4 * 4] = s;
        } else if (by == 0) {
            *(float4*)&g_cp[(size_t)(row0 + r) * DSTATE + (c4 - 4) * 4] = s;
        }
    }
    // ---- load dtw tile ----
#pragma unroll
    for (int i = 0; i < 8; i++) {
        int e  = i * 256 + tid;
        int c  = e >> 4;
        int k4 = e & 15;
        float4 v = *(const float4*)&dtw[(size_t)(by * 128 + c) * DTRANK + k4 * 4];
        ws[k4 * 4 + 0][c] = v.x;
        ws[k4 * 4 + 1][c] = v.y;
        ws[k4 * 4 + 2][c] = v.z;
        ws[k4 * 4 + 3][c] = v.w;
    }
    __syncthreads();

    // ---- Phase B: f32x2 GEMM (LDS.128 weight reads) ----
    ull accp[2][4];
#pragma unroll
    for (int i = 0; i < 2; i++)
#pragma unroll
        for (int j = 0; j < 4; j++) accp[i][j] = 0ull;

#pragma unroll 16
    for (int k = 0; k < 64; k++) {
        float2 a01 = *(const float2*)&dps[k][ty * 2];
        ull a0p = pack2(a01.x, a01.x);
        ull a1p = pack2(a01.y, a01.y);
        ulonglong2 w01 = *(const ulonglong2*)&ws[k][tx * 8];
        ulonglong2 w23 = *(const ulonglong2*)&ws[k][tx * 8 + 4];
        accp[0][0] = fma2(a0p, w01.x, accp[0][0]);
        accp[0][1] = fma2(a0p, w01.y, accp[0][1]);
        accp[0][2] = fma2(a0p, w23.x, accp[0][2]);
        accp[0][3] = fma2(a0p, w23.y, accp[0][3]);
        accp[1][0] = fma2(a1p, w01.x, accp[1][0]);
        accp[1][1] = fma2(a1p, w01.y, accp[1][1]);
        accp[1][2] = fma2(a1p, w23.x, accp[1][2]);
        accp[1][3] = fma2(a1p, w23.y, accp[1][3]);
    }
    __syncthreads();   // done reading ws; region becomes sdd

    // ---- Phase C: epilogue (fast softplus, smem sig/dtb) ----
#pragma unroll
    for (int i = 0; i < 2; i++) {
        int lloc = ty * 2 + i;
        int r    = row0 + lloc;
        int c0   = by * 128 + tx * 8;
        float4 x0 = *(const float4*)&x[(size_t)r * DMODEL + c0];
        float4 x1 = *(const float4*)&x[(size_t)r * DMODEL + c0 + 4];
        float xv[8] = {x0.x, x0.y, x0.z, x0.w, x1.x, x1.y, x1.z, x1.w};
        float dl[8], du[8];
#pragma unroll
        for (int jp = 0; jp < 4; jp++) {
            float v0, v1;
            unpack2(accp[i][jp], v0, v1);
            float av[2] = {v0, v1};
#pragma unroll
            for (int h = 0; h < 2; h++) {
                int j = jp * 2 + h;
                int cl = tx * 8 + j;
                float u  = xv[j] * ssg[cl];
                float v  = av[h] + sdtb[cl];
                float delta = fmaxf(v, 0.f) + __logf(1.f + __expf(-fabsf(v)));
                dl[j] = delta;
                du[j] = delta * u;
            }
        }
        float4* dst = (float4*)&g_dd[(size_t)r * DMODEL + c0];
#pragma unroll
        for (int j = 0; j < 4; j++) {
            float4 pk = make_float4(dl[2*j], du[2*j], dl[2*j+1], du[2*j+1]);
            dst[j] = pk;
            *(float4*)&sdd[lloc][tx * 8 + j * 2] = pk;
        }
    }
    __syncthreads();

    // ---- Phase D: chunk-local scan (chunk-major output) ----
    {
        const int dloc = tid & 127;
        const int nh   = tid >> 7;
        const int b    = row0 >> 11;
        const int chunk= (row0 >> 5) & (NCHUNK - 1);
        const int d    = by * 128 + dloc;
        const size_t base = (size_t)chunk * NCH + b * DMODEL + d;

        float A[8];
#pragma unroll
        for (int j = 0; j < 8; j++) A[j] = g_A[(size_t)d * DSTATE + nh * 8 + j];
        bool uniform = true;
#pragma unroll
        for (int j = 1; j < 8; j++) uniform &= (A[j] == A[0]);

        ull hp[4] = {0ull, 0ull, 0ull, 0ull};
        float T = 0.f;

        if (uniform) {
            const float A0 = A[0];
#pragma unroll 4
            for (int l = 0; l < CLEN; l++) {
                float2 t = sdd[l][dloc];
                T += t.x;
                float a = __expf(t.x * A0);
                ull ap  = pack2(a, a);
                ull dup = pack2(t.y, t.y);
                ulonglong2 b01 = *(const ulonglong2*)&Bs[l][nh * 8];
                ulonglong2 b23 = *(const ulonglong2*)&Bs[l][nh * 8 + 4];
                hp[0] = fma2(ap, hp[0], mul2(dup, b01.x));
                hp[1] = fma2(ap, hp[1], mul2(dup, b01.y));
                hp[2] = fma2(ap, hp[2], mul2(dup, b23.x));
                hp[3] = fma2(ap, hp[3], mul2(dup, b23.y));
            }
        } else {
#pragma unroll 2
            for (int l = 0; l < CLEN; l++) {
                float2 t = sdd[l][dloc];
                T += t.x;
                ull dup = pack2(t.y, t.y);
                ulonglong2 b01 = *(const ulonglong2*)&Bs[l][nh * 8];
                ulonglong2 b23 = *(const ulonglong2*)&Bs[l][nh * 8 + 4];
                ull bb[4] = {b01.x, b01.y, b23.x, b23.y};
#pragma unroll
                for (int p = 0; p < 4; p++) {
                    ull ap = pack2(__expf(t.x * A[p*2]), __expf(t.x * A[p*2+1]));
                    hp[p] = fma2(ap, hp[p], mul2(dup, bb[p]));
                }
            }
        }
#pragma unroll
        for (int p = 0; p < 4; p++)
            *(ull*)&g_hl[base * DSTATE + nh * 8 + p * 2] = hp[p];
        if (nh == 0) g_T[base] = T;
    }
}

// ---------------------------------------------------------------------------
// K3 (pass B): chunk combine, double-buffered prefetch across gblks.
// ---------------------------------------------------------------------------
__global__ __launch_bounds__(256)
void scanB_kernel()
{
    const int idx = blockIdx.x * 256 + threadIdx.x;   // 32768
    const int ch  = idx >> 4;
    const int n   = idx & 15;
    const int d   = ch & (DMODEL - 1);

    const float A = g_A[(size_t)d * DSTATE + n];

    float hl[2][8], Tv[2][8];
#pragma unroll
    for (int i = 0; i < 8; i++) {
        hl[0][i] = g_hl[((size_t)i * NCH + ch) * DSTATE + n];
        Tv[0][i] = g_T [(size_t)i * NCH + ch];
    }

    float hin = 0.f;
#pragma unroll
    for (int g = 0; g < 8; g++) {
        const int cur = g & 1, nxt = cur ^ 1;
        if (g < 7) {
#pragma unroll
            for (int i = 0; i < 8; i++) {
                hl[nxt][i] = g_hl[((size_t)(g * 8 + 8 + i) * NCH + ch) * DSTATE + n];
                Tv[nxt][i] = g_T [(size_t)(g * 8 + 8 + i) * NCH + ch];
            }
        }
        float a8[8];
#pragma unroll
        for (int i = 0; i < 8; i++) a8[i] = __expf(Tv[cur][i] * A);
#pragma unroll
        for (int i = 0; i < 8; i++) {
            g_hin[((size_t)(g * 8 + i) * NCH + ch) * DSTATE + n] = hin;
            hin = fmaf(hin, a8[i], hl[cur][i]);
        }
    }
}

// ---------------------------------------------------------------------------
// K4 (pass C): full re-scan with correct h0; LDS.128 B/C reads; MLP=8.
// ---------------------------------------------------------------------------
__global__ __launch_bounds__(256)
void scanC_kernel(const float* __restrict__ Dp,
                  float* __restrict__ out)
{
    __shared__ float Bs[CLEN][DSTATE];
    __shared__ float Cs[CLEN][DSTATE];

    const int tid   = threadIdx.x;
    const int blk   = blockIdx.x;
    const int b     = blk >> 8;
    const int rem   = blk & 255;
    const int dgrp  = rem >> 6;
    const int chunk = rem & 63;
    const int d     = dgrp * 256 + tid;
    const int ch    = b * DMODEL + d;
    const int l0    = chunk * CLEN;
    const size_t hbase = ((size_t)chunk * NCH + ch) * DSTATE;

    if (tid < CLEN * DSTATE / 4) {
        const float4* sb = (const float4*)&g_bp[((size_t)b * SEQLEN + l0) * DSTATE];
        ((float4*)Bs)[tid] = sb[tid];
    } else if (tid < CLEN * DSTATE / 2) {
        const float4* sc = (const float4*)&g_cp[((size_t)b * SEQLEN + l0) * DSTATE];
        ((float4*)Cs)[tid - CLEN * DSTATE / 4] = sc[tid - CLEN * DSTATE / 4];
    }

    float A[DSTATE];
#pragma unroll
    for (int n = 0; n < DSTATE; n++) A[n] = g_A[(size_t)d * DSTATE + n];
    bool uniform = true;
#pragma unroll
    for (int n = 1; n < DSTATE; n++) uniform &= (A[n] == A[0]);

    ull hp[8];
#pragma unroll
    for (int p = 0; p < 8; p++)
        hp[p] = *(const ull*)&g_hin[hbase + p * 2];

    const float Dpd = Dp[d];

    const float2* __restrict__ dd = g_dd + ((size_t)b * SEQLEN + l0) * DMODEL + d;
    float*        __restrict__ op = out  + ((size_t)b * SEQLEN + l0) * DMODEL + d;
    __syncthreads();

    if (uniform) {
        const float A0 = A[0];
        for (int lb = 0; lb < CLEN / 8; lb++) {
            float2 t[8];
#pragma unroll
            for (int i = 0; i < 8; i++) t[i] = dd[(size_t)(lb * 8 + i) * DMODEL];
            float a[8], u[8];
#pragma unroll
            for (int i = 0; i < 8; i++) {
                a[i] = __expf(t[i].x * A0);
                u[i] = __fdividef(t[i].y, fmaxf(t[i].x, 1e-38f));
            }
#pragma unroll
            for (int i = 0; i < 8; i++) {
                int l = lb * 8 + i;
                ull ap  = pack2(a[i], a[i]);
                ull dup = pack2(t[i].y, t[i].y);
                ull yp  = 0ull;
                const ulonglong2* bl = (const ulonglong2*)&Bs[l][0];
                const ulonglong2* cl = (const ulonglong2*)&Cs[l][0];
#pragma unroll
                for (int q = 0; q < 4; q++) {
                    ulonglong2 bq = bl[q];
                    ulonglong2 cq = cl[q];
                    hp[2*q+0] = fma2(ap, hp[2*q+0], mul2(dup, bq.x));
                    yp        = fma2(hp[2*q+0], cq.x, yp);
                    hp[2*q+1] = fma2(ap, hp[2*q+1], mul2(dup, bq.y));
                    yp        = fma2(hp[2*q+1], cq.y, yp);
                }
                float ylo, yhi;
                unpack2(yp, ylo, yhi);
                op[(size_t)l * DMODEL] = fmaf(u[i], Dpd, ylo + yhi);
            }
        }
    } else {
        for (int lb = 0; lb < CLEN / 8; lb++) {
            float2 t[8];
#pragma unroll
            for (int i = 0; i < 8; i++) t[i] = dd[(size_t)(lb * 8 + i) * DMODEL];
            float u[8];
#pragma unroll
            for (int i = 0; i < 8; i++)
                u[i] = __fdividef(t[i].y, fmaxf(t[i].x, 1e-38f));
#pragma unroll
            for (int i = 0; i < 8; i++) {
                int l = lb * 8 + i;
                ull dup = pack2(t[i].y, t[i].y);
                ull yp  = 0ull;
                const ulonglong2* bl = (const ulonglong2*)&Bs[l][0];
                const ulonglong2* cl = (const ulonglong2*)&Cs[l][0];
#pragma unroll
                for (int q = 0; q < 4; q++) {
                    ulonglong2 bq = bl[q];
                    ulonglong2 cq = cl[q];
                    ull ap0 = pack2(__expf(t[i].x * A[4*q+0]), __expf(t[i].x * A[4*q+1]));
                    ull ap1 = pack2(__expf(t[i].x * A[4*q+2]), __expf(t[i].x * A[4*q+3]));
                    hp[2*q+0] = fma2(ap0, hp[2*q+0], mul2(dup, bq.x));
                    yp        = fma2(hp[2*q+0], cq.x, yp);
                    hp[2*q+1] = fma2(ap1, hp[2*q+1], mul2(dup, bq.y));
                    yp        = fma2(hp[2*q+1], cq.y, yp);
                }
                float ylo, yhi;
                unpack2(yp, ylo, yhi);
                op[(size_t)l * DMODEL] = fmaf(u[i], Dpd, ylo + yhi);
            }
        }
    }
}

// ---------------------------------------------------------------------------
// Launch
// ---------------------------------------------------------------------------
extern "C" void kernel_launch(void* const* d_in, const int* in_sizes, int n_in,
                              void* d_out, int out_size)
{
    const float* x    = (const float*)d_in[0];
    const float* Alog = (const float*)d_in[1];
    const float* xpw  = (const float*)d_in[2];
    const float* dtw  = (const float*)d_in[3];
    const float* dtb  = (const float*)d_in[4];
    const float* Dp   = (const float*)d_in[5];
    const float* te   = (const float*)d_in[6];
    float* out = (float*)d_out;

    prep_kernel  <<<(96 * DMODEL + 255) / 256, 256>>>(xpw, te, Alog);
    gemm1_kernel <<<dim3(NROWS / 64, KSPLIT), 256>>>(x);
    gemm2s_kernel<<<dim3(NROWS / 32, DMODEL / 128), 256>>>(x, dtw, dtb, te);
    scanB_kernel <<<(NCH * DSTATE) / 256, 256>>>();
    scanC_kernel <<<BATCH * 4 * NCHUNK, 256>>>(Dp, out);
}

// round 10
// speedup vs baseline: 1.0625x; 1.0625x over previous
#include <cuda_runtime.h>
#include <cuda_bf16.h>
#include <cstdint>

#define BATCH   2
#define SEQLEN  2048
#define DMODEL  1024
#define DSTATE  16
#define DTRANK  64
#define NROWS   (BATCH * SEQLEN)          // 4096
#define NCHUNK  64
#define CLEN    (SEQLEN / NCHUNK)         // 32
#define NCH     (BATCH * DMODEL)          // 2048
#define NGRP    (NCH * NCHUNK)            // 131072
#define KSPLIT  4
#define SCAN_GRID 512

typedef unsigned long long ull;

// ---------------------------------------------------------------------------
// f32x2 packed-math helpers
// ---------------------------------------------------------------------------
__device__ __forceinline__ ull pack2(float lo, float hi) {
    ull r; asm("mov.b64 %0, {%1, %2};" : "=l"(r) : "f"(lo), "f"(hi)); return r;
}
__device__ __forceinline__ void unpack2(ull v, float& lo, float& hi) {
    asm("mov.b64 {%0, %1}, %2;" : "=f"(lo), "=f"(hi) : "l"(v));
}
__device__ __forceinline__ ull fma2(ull a, ull b, ull c) {
    ull d; asm("fma.rn.f32x2 %0, %1, %2, %3;" : "=l"(d) : "l"(a), "l"(b), "l"(c)); return d;
}
__device__ __forceinline__ ull mul2(ull a, ull b) {
    ull d; asm("mul.rn.f32x2 %0, %1, %2;" : "=l"(d) : "l"(a), "l"(b)); return d;
}

// ---------------------------------------------------------------------------
// Device scratch.  Boundary-state arrays are CHUNK-MAJOR: [chunk][ch][n]
// ---------------------------------------------------------------------------
__device__ float  g_dpp[(size_t)KSPLIT * NROWS * DTRANK];
__device__ float  g_bcp[(size_t)KSPLIT * NROWS * 32];
__device__ float  g_bp [(size_t)NROWS * DSTATE];
__device__ float  g_cp [(size_t)NROWS * DSTATE];
__device__ float2 g_dd [(size_t)NROWS * DMODEL];
__device__ float  g_hl [(size_t)NGRP * DSTATE];
__device__ float  g_T  [(size_t)NGRP];
__device__ float  g_hin[(size_t)NGRP * DSTATE];
// spin-barrier state (graph-replay-safe: flag monotonically increases)
__device__ unsigned g_barcnt  = 0;
__device__ unsigned g_barflag = 0;

// ---------------------------------------------------------------------------
// K1: split-K GEMM1 partials.  BM=64, BN=96, BK=64, 256 thr, tile 4x6 (f32x2)
//   sig(te) folded in at the W-tile load (prep kernel eliminated).
// ---------------------------------------------------------------------------
__global__ __launch_bounds__(256)
void gemm1_kernel(const float* __restrict__ x,
                  const float* __restrict__ W,
                  const float* __restrict__ te)
{
    __shared__ float As[64][68];
    __shared__ float Ws[64][98];
    __shared__ float ssg[DMODEL];

    const int tid  = threadIdx.x;
    const int row0 = blockIdx.x * 64;
    const int ks   = blockIdx.y;
    const int ty   = tid >> 4;
    const int tx   = tid & 15;

#pragma unroll
    for (int i = 0; i < 4; i++) {
        int k = i * 256 + tid;
        ssg[k] = 1.f / (1.f + __expf(-te[k]));
    }
    __syncthreads();

    ull accp[4][3];
#pragma unroll
    for (int i = 0; i < 4; i++)
#pragma unroll
        for (int j = 0; j < 3; j++) accp[i][j] = 0ull;

    for (int kk = 0; kk < 256; kk += 64) {
        const int kt = ks * 256 + kk;
#pragma unroll
        for (int i = 0; i < 4; i++) {
            int e  = i * 256 + tid;
            int r  = e >> 4;
            int k4 = e & 15;
            float4 v = *(const float4*)&x[(size_t)(row0 + r) * DMODEL + kt + k4 * 4];
            As[k4 * 4 + 0][r] = v.x;
            As[k4 * 4 + 1][r] = v.y;
            As[k4 * 4 + 2][r] = v.z;
            As[k4 * 4 + 3][r] = v.w;
        }
#pragma unroll
        for (int i = 0; i < 6; i++) {
            int e  = i * 256 + tid;
            int c  = e >> 4;
            int k4 = e & 15;
            float4 v = *(const float4*)&W[(size_t)c * DMODEL + kt + k4 * 4];
            Ws[k4 * 4 + 0][c] = v.x * ssg[kt + k4 * 4 + 0];
            Ws[k4 * 4 + 1][c] = v.y * ssg[kt + k4 * 4 + 1];
            Ws[k4 * 4 + 2][c] = v.z * ssg[kt + k4 * 4 + 2];
            Ws[k4 * 4 + 3][c] = v.w * ssg[kt + k4 * 4 + 3];
        }
        __syncthreads();

#pragma unroll 8
        for (int k = 0; k < 64; k++) {
            float4 a4 = *(const float4*)&As[k][ty * 4];
            ull ap[4];
            ap[0] = pack2(a4.x, a4.x);
            ap[1] = pack2(a4.y, a4.y);
            ap[2] = pack2(a4.z, a4.z);
            ap[3] = pack2(a4.w, a4.w);
            ull wp0 = *(const ull*)&Ws[k][tx * 6 + 0];
            ull wp1 = *(const ull*)&Ws[k][tx * 6 + 2];
            ull wp2 = *(const ull*)&Ws[k][tx * 6 + 4];
#pragma unroll
            for (int i = 0; i < 4; i++) {
                accp[i][0] = fma2(ap[i], wp0, accp[i][0]);
                accp[i][1] = fma2(ap[i], wp1, accp[i][1]);
                accp[i][2] = fma2(ap[i], wp2, accp[i][2]);
            }
        }
        __syncthreads();
    }

#pragma unroll
    for (int i = 0; i < 4; i++) {
        int r = row0 + ty * 4 + i;
#pragma unroll
        for (int jp = 0; jp < 3; jp++) {
            float v0, v1;
            unpack2(accp[i][jp], v0, v1);
            int c = tx * 6 + jp * 2;
#pragma unroll
            for (int h = 0; h < 2; h++) {
                float v = h ? v1 : v0;
                int cc = c + h;
                if (cc < DTRANK)
                    g_dpp[((size_t)ks * NROWS + r) * DTRANK + cc] = v;
                else
                    g_bcp[((size_t)ks * NROWS + r) * 32 + (cc - DTRANK)] = v;
            }
        }
    }
}

// ---------------------------------------------------------------------------
// K2 (fused GEMM2 + chunk-local scan), chunk-major state output.
// ---------------------------------------------------------------------------
__global__ __launch_bounds__(256)
void gemm2s_kernel(const float* __restrict__ x,
                   const float* __restrict__ dtw,
                   const float* __restrict__ dtb,
                   const float* __restrict__ te,
                   const float* __restrict__ A_log)
{
    __shared__ __align__(16) char smraw[45568];
    float  (*dps)[34]  = (float (*)[34]) (smraw);                // 8704 B
    float  (*ws)[132]  = (float (*)[132])(smraw + 8704);         // 33792 B
    float2 (*sdd)[132] = (float2(*)[132])(smraw + 8704);         // union w/ ws
    float  (*Bs)[16]   = (float (*)[16]) (smraw + 42496);        // 2048 B
    float*  ssg        = (float*)(smraw + 44544);                // 512 B
    float*  sdtb       = (float*)(smraw + 45056);                // 512 B

    const int tid  = threadIdx.x;
    const int row0 = blockIdx.x * 32;
    const int by   = blockIdx.y;
    const int ty   = tid >> 4;
    const int tx   = tid & 15;

    if (tid < 128) {
        float tev = te[by * 128 + tid];
        ssg[tid]  = 1.f / (1.f + __expf(-tev));
        sdtb[tid] = dtb[by * 128 + tid];
    }

    // ---- Phase A: sum partials ----
#pragma unroll
    for (int i = 0; i < 2; i++) {
        int e  = i * 256 + tid;
        int r  = e >> 4;
        int k4 = e & 15;
        float4 s = make_float4(0.f, 0.f, 0.f, 0.f);
#pragma unroll
        for (int ks = 0; ks < KSPLIT; ks++) {
            float4 v = *(const float4*)&g_dpp[((size_t)ks * NROWS + row0 + r) * DTRANK + k4 * 4];
            s.x += v.x; s.y += v.y; s.z += v.z; s.w += v.w;
        }
        dps[k4 * 4 + 0][r] = s.x;
        dps[k4 * 4 + 1][r] = s.y;
        dps[k4 * 4 + 2][r] = s.z;
        dps[k4 * 4 + 3][r] = s.w;
    }
    {
        int r  = tid >> 3;
        int c4 = tid & 7;
        float4 s = make_float4(0.f, 0.f, 0.f, 0.f);
#pragma unroll
        for (int ks = 0; ks < KSPLIT; ks++) {
            float4 v = *(const float4*)&g_bcp[((size_t)ks * NROWS + row0 + r) * 32 + c4 * 4];
            s.x += v.x; s.y += v.y; s.z += v.z; s.w += v.w;
        }
        if (c4 < 4) {
            *(float4*)&Bs[r][c4 * 4] = s;
            if (by == 0) *(float4*)&g_bp[(size_t)(row0 + r) * DSTATE + c4 * 4] = s;
        } else if (by == 0) {
            *(float4*)&g_cp[(size_t)(row0 + r) * DSTATE + (c4 - 4) * 4] = s;
        }
    }
#pragma unroll
    for (int i = 0; i < 8; i++) {
        int e  = i * 256 + tid;
        int c  = e >> 4;
        int k4 = e & 15;
        float4 v = *(const float4*)&dtw[(size_t)(by * 128 + c) * DTRANK + k4 * 4];
        ws[k4 * 4 + 0][c] = v.x;
        ws[k4 * 4 + 1][c] = v.y;
        ws[k4 * 4 + 2][c] = v.z;
        ws[k4 * 4 + 3][c] = v.w;
    }
    __syncthreads();

    // ---- Phase B: f32x2 GEMM ----
    ull accp[2][4];
#pragma unroll
    for (int i = 0; i < 2; i++)
#pragma unroll
        for (int j = 0; j < 4; j++) accp[i][j] = 0ull;

#pragma unroll 16
    for (int k = 0; k < 64; k++) {
        float2 a01 = *(const float2*)&dps[k][ty * 2];
        ull a0p = pack2(a01.x, a01.x);
        ull a1p = pack2(a01.y, a01.y);
        ulonglong2 w01 = *(const ulonglong2*)&ws[k][tx * 8];
        ulonglong2 w23 = *(const ulonglong2*)&ws[k][tx * 8 + 4];
        accp[0][0] = fma2(a0p, w01.x, accp[0][0]);
        accp[0][1] = fma2(a0p, w01.y, accp[0][1]);
        accp[0][2] = fma2(a0p, w23.x, accp[0][2]);
        accp[0][3] = fma2(a0p, w23.y, accp[0][3]);
        accp[1][0] = fma2(a1p, w01.x, accp[1][0]);
        accp[1][1] = fma2(a1p, w01.y, accp[1][1]);
        accp[1][2] = fma2(a1p, w23.x, accp[1][2]);
        accp[1][3] = fma2(a1p, w23.y, accp[1][3]);
    }
    __syncthreads();

    // ---- Phase C: epilogue ----
#pragma unroll
    for (int i = 0; i < 2; i++) {
        int lloc = ty * 2 + i;
        int r    = row0 + lloc;
        int c0   = by * 128 + tx * 8;
        float4 x0 = *(const float4*)&x[(size_t)r * DMODEL + c0];
        float4 x1 = *(const float4*)&x[(size_t)r * DMODEL + c0 + 4];
        float xv[8] = {x0.x, x0.y, x0.z, x0.w, x1.x, x1.y, x1.z, x1.w};
        float dl[8], du[8];
#pragma unroll
        for (int jp = 0; jp < 4; jp++) {
            float v0, v1;
            unpack2(accp[i][jp], v0, v1);
            float av[2] = {v0, v1};
#pragma unroll
            for (int h = 0; h < 2; h++) {
                int j = jp * 2 + h;
                int cl = tx * 8 + j;
                float u  = xv[j] * ssg[cl];
                float v  = av[h] + sdtb[cl];
                float delta = fmaxf(v, 0.f) + __logf(1.f + __expf(-fabsf(v)));
                dl[j] = delta;
                du[j] = delta * u;
            }
        }
        float4* dst = (float4*)&g_dd[(size_t)r * DMODEL + c0];
#pragma unroll
        for (int j = 0; j < 4; j++) {
            float4 pk = make_float4(dl[2*j], du[2*j], dl[2*j+1], du[2*j+1]);
            dst[j] = pk;
            *(float4*)&sdd[lloc][tx * 8 + j * 2] = pk;
        }
    }
    __syncthreads();

    // ---- Phase D: chunk-local scan (chunk-major output) ----
    {
        const int dloc = tid & 127;
        const int nh   = tid >> 7;
        const int b    = row0 >> 11;
        const int chunk= (row0 >> 5) & (NCHUNK - 1);
        const int d    = by * 128 + dloc;
        const size_t base = (size_t)chunk * NCH + b * DMODEL + d;

        float A[8];
#pragma unroll
        for (int j = 0; j < 8; j++) A[j] = -__expf(A_log[(size_t)d * DSTATE + nh * 8 + j]);
        bool uniform = true;
#pragma unroll
        for (int j = 1; j < 8; j++) uniform &= (A[j] == A[0]);

        ull hp[4] = {0ull, 0ull, 0ull, 0ull};
        float T = 0.f;

        if (uniform) {
            const float A0 = A[0];
#pragma unroll 4
            for (int l = 0; l < CLEN; l++) {
                float2 t = sdd[l][dloc];
                T += t.x;
                float a = __expf(t.x * A0);
                ull ap  = pack2(a, a);
                ull dup = pack2(t.y, t.y);
                ulonglong2 b01 = *(const ulonglong2*)&Bs[l][nh * 8];
                ulonglong2 b23 = *(const ulonglong2*)&Bs[l][nh * 8 + 4];
                hp[0] = fma2(ap, hp[0], mul2(dup, b01.x));
                hp[1] = fma2(ap, hp[1], mul2(dup, b01.y));
                hp[2] = fma2(ap, hp[2], mul2(dup, b23.x));
                hp[3] = fma2(ap, hp[3], mul2(dup, b23.y));
            }
        } else {
#pragma unroll 2
            for (int l = 0; l < CLEN; l++) {
                float2 t = sdd[l][dloc];
                T += t.x;
                ull dup = pack2(t.y, t.y);
                ulonglong2 b01 = *(const ulonglong2*)&Bs[l][nh * 8];
                ulonglong2 b23 = *(const ulonglong2*)&Bs[l][nh * 8 + 4];
                ull bb[4] = {b01.x, b01.y, b23.x, b23.y};
#pragma unroll
                for (int p = 0; p < 4; p++) {
                    ull ap = pack2(__expf(t.x * A[p*2]), __expf(t.x * A[p*2+1]));
                    hp[p] = fma2(ap, hp[p], mul2(dup, bb[p]));
                }
            }
        }
#pragma unroll
        for (int p = 0; p < 4; p++)
            *(ull*)&g_hl[base * DSTATE + nh * 8 + p * 2] = hp[p];
        if (nh == 0) g_T[base] = T;
    }
}

// ---------------------------------------------------------------------------
// K3 (fused pass B + pass C, device-wide spin barrier between them).
//   Phase B: 4 threads per (ch,n) pair compose 16 affine chunk-maps each,
//            smem exclusive prefix over quarters, emit g_hin.
//   Phase C: full re-scan (as before), direct coalesced output.
//   512 blocks x 256 thr, 4 blocks/SM guaranteed resident -> barrier safe.
// ---------------------------------------------------------------------------
__global__ __launch_bounds__(256, 4)
void scanBC_kernel(const float* __restrict__ A_log,
                   const float* __restrict__ Dp,
                   float* __restrict__ out)
{
    __shared__ __align__(16) float sm[CLEN * DSTATE * 2];   // 4KB (union B/C usage)

    const int tid  = threadIdx.x;
    const unsigned gen0 = *(volatile unsigned*)&g_barflag;

    // ================= Phase B: boundary combine =================
    {
        const int idx = blockIdx.x * 256 + tid;   // 0..131071
        const int ch  = idx >> 6;                  // 2048
        const int q   = (idx >> 4) & 3;            // quarter
        const int n   = idx & 15;
        const int d   = ch & (DMODEL - 1);

        const float A = -__expf(A_log[(size_t)d * DSTATE + n]);

        float a[16], hl[16];
#pragma unroll
        for (int i = 0; i < 16; i++) {
            int c = q * 16 + i;
            hl[i] = g_hl[((size_t)c * NCH + ch) * DSTATE + n];
            a[i]  = g_T [(size_t)c * NCH + ch];
        }
#pragma unroll
        for (int i = 0; i < 16; i++) a[i] = __expf(a[i] * A);

        // compose this quarter's 16 maps: h -> Aa*h + Bb
        float Aa = 1.f, Bb = 0.f;
#pragma unroll
        for (int i = 0; i < 16; i++) {
            Bb = fmaf(a[i], Bb, hl[i]);
            Aa *= a[i];
        }
        const int chl = tid >> 6;                  // 0..3 local channel
        float2* smq = (float2*)sm;                 // [chl][q][n]
        smq[(chl * 4 + q) * 16 + n] = make_float2(Aa, Bb);
        __syncthreads();

        // exclusive prefix over quarters (h0 = 0 globally)
        float hin = 0.f;
#pragma unroll
        for (int qq = 0; qq < 3; qq++) {
            if (qq < q) {
                float2 m = smq[(chl * 4 + qq) * 16 + n];
                hin = fmaf(m.x, hin, m.y);
            }
        }
        // walk this quarter, writing incoming states
#pragma unroll
        for (int i = 0; i < 16; i++) {
            int c = q * 16 + i;
            g_hin[((size_t)c * NCH + ch) * DSTATE + n] = hin;
            hin = fmaf(a[i], hin, hl[i]);
        }
    }

    // ================= device-wide barrier =================
    __threadfence();
    __syncthreads();
    if (tid == 0) {
        unsigned old = atomicAdd(&g_barcnt, 1u);
        if (old == gridDim.x - 1) {
            g_barcnt = 0;
            __threadfence();
            atomicAdd(&g_barflag, 1u);
        } else {
            while (*(volatile unsigned*)&g_barflag == gen0) { }
        }
    }
    __syncthreads();
    __threadfence();

    // ================= Phase C: full re-scan =================
    {
        float (*Bs)[DSTATE] = (float(*)[DSTATE])sm;
        float (*Cs)[DSTATE] = (float(*)[DSTATE])(sm + CLEN * DSTATE);

        const int blk   = blockIdx.x;
        const int b     = blk >> 8;
        const int rem   = blk & 255;
        const int dgrp  = rem >> 6;
        const int chunk = rem & 63;
        const int d     = dgrp * 256 + tid;
        const int ch    = b * DMODEL + d;
        const int l0    = chunk * CLEN;
        const size_t hbase = ((size_t)chunk * NCH + ch) * DSTATE;

        if (tid < CLEN * DSTATE / 4) {
            const float4* sb = (const float4*)&g_bp[((size_t)b * SEQLEN + l0) * DSTATE];
            ((float4*)Bs)[tid] = sb[tid];
        } else if (tid < CLEN * DSTATE / 2) {
            const float4* sc = (const float4*)&g_cp[((size_t)b * SEQLEN + l0) * DSTATE];
            ((float4*)Cs)[tid - CLEN * DSTATE / 4] = sc[tid - CLEN * DSTATE / 4];
        }

        float A[DSTATE];
#pragma unroll
        for (int n = 0; n < DSTATE; n++) A[n] = -__expf(A_log[(size_t)d * DSTATE + n]);
        bool uniform = true;
#pragma unroll
        for (int n = 1; n < DSTATE; n++) uniform &= (A[n] == A[0]);

        ull hp[8];
#pragma unroll
        for (int p = 0; p < 8; p++)
            hp[p] = *(const ull*)&g_hin[hbase + p * 2];

        const float Dpd = Dp[d];

        const float2* __restrict__ dd = g_dd + ((size_t)b * SEQLEN + l0) * DMODEL + d;
        float*        __restrict__ op = out  + ((size_t)b * SEQLEN + l0) * DMODEL + d;
        __syncthreads();

        if (uniform) {
            const float A0 = A[0];
            for (int lb = 0; lb < CLEN / 8; lb++) {
                float2 t[8];
#pragma unroll
                for (int i = 0; i < 8; i++) t[i] = dd[(size_t)(lb * 8 + i) * DMODEL];
                float av[8], u[8];
#pragma unroll
                for (int i = 0; i < 8; i++) {
                    av[i] = __expf(t[i].x * A0);
                    u[i]  = __fdividef(t[i].y, fmaxf(t[i].x, 1e-38f));
                }
#pragma unroll
                for (int i = 0; i < 8; i++) {
                    int l = lb * 8 + i;
                    ull ap  = pack2(av[i], av[i]);
                    ull dup = pack2(t[i].y, t[i].y);
                    ull yp  = 0ull;
                    const ulonglong2* bl = (const ulonglong2*)&Bs[l][0];
                    const ulonglong2* cl = (const ulonglong2*)&Cs[l][0];
#pragma unroll
                    for (int qd = 0; qd < 4; qd++) {
                        ulonglong2 bq = bl[qd];
                        ulonglong2 cq = cl[qd];
                        hp[2*qd+0] = fma2(ap, hp[2*qd+0], mul2(dup, bq.x));
                        yp         = fma2(hp[2*qd+0], cq.x, yp);
                        hp[2*qd+1] = fma2(ap, hp[2*qd+1], mul2(dup, bq.y));
                        yp         = fma2(hp[2*qd+1], cq.y, yp);
                    }
                    float ylo, yhi;
                    unpack2(yp, ylo, yhi);
                    op[(size_t)l * DMODEL] = fmaf(u[i], Dpd, ylo + yhi);
                }
            }
        } else {
            for (int lb = 0; lb < CLEN / 8; lb++) {
                float2 t[8];
#pragma unroll
                for (int i = 0; i < 8; i++) t[i] = dd[(size_t)(lb * 8 + i) * DMODEL];
                float u[8];
#pragma unroll
                for (int i = 0; i < 8; i++)
                    u[i] = __fdividef(t[i].y, fmaxf(t[i].x, 1e-38f));
#pragma unroll
                for (int i = 0; i < 8; i++) {
                    int l = lb * 8 + i;
                    ull dup = pack2(t[i].y, t[i].y);
                    ull yp  = 0ull;
                    const ulonglong2* bl = (const ulonglong2*)&Bs[l][0];
                    const ulonglong2* cl = (const ulonglong2*)&Cs[l][0];
#pragma unroll
                    for (int qd = 0; qd < 4; qd++) {
                        ulonglong2 bq = bl[qd];
                        ulonglong2 cq = cl[qd];
                        ull ap0 = pack2(__expf(t[i].x * A[4*qd+0]), __expf(t[i].x * A[4*qd+1]));
                        ull ap1 = pack2(__expf(t[i].x * A[4*qd+2]), __expf(t[i].x * A[4*qd+3]));
                        hp[2*qd+0] = fma2(ap0, hp[2*qd+0], mul2(dup, bq.x));
                        yp         = fma2(hp[2*qd+0], cq.x, yp);
                        hp[2*qd+1] = fma2(ap1, hp[2*qd+1], mul2(dup, bq.y));
                        yp         = fma2(hp[2*qd+1], cq.y, yp);
                    }
                    float ylo, yhi;
                    unpack2(yp, ylo, yhi);
                    op[(size_t)l * DMODEL] = fmaf(u[i], Dpd, ylo + yhi);
                }
            }
        }
    }
}

// ---------------------------------------------------------------------------
// Launch: 3 kernels total
// ---------------------------------------------------------------------------
extern "C" void kernel_launch(void* const* d_in, const int* in_sizes, int n_in,
                              void* d_out, int out_size)
{
    const float* x    = (const float*)d_in[0];
    const float* Alog = (const float*)d_in[1];
    const float* xpw  = (const float*)d_in[2];
    const float* dtw  = (const float*)d_in[3];
    const float* dtb  = (const float*)d_in[4];
    const float* Dp   = (const float*)d_in[5];
    const float* te   = (const float*)d_in[6];
    float* out = (float*)d_out;

    gemm1_kernel <<<dim3(NROWS / 64, KSPLIT), 256>>>(x, xpw, te);
    gemm2s_kernel<<<dim3(NROWS / 32, DMODEL / 128), 256>>>(x, dtw, dtb, te, Alog);
    scanBC_kernel<<<SCAN_GRID, 256>>>(Alog, Dp, out);
}